// round 15
// baseline (speedup 1.0000x reference)
#include <cuda_runtime.h>
#include <cuda_fp16.h>
#include <cuda_bf16.h>
#include <math.h>

#define B_  4096
#define T_  256
#define E_  96
#define H_  6
#define HD_ 16
#define V_  98
#define EP  100     // padded row stride (halves) for Ek/Ev/Pk/Pv tables
#define GO  384     // stage-1 fused outputs: [r|z (192) | i_n (96) | h_n (96)]
#define S2O 224     // stage-2 padded outputs: [cand(96) | p(1) | head(98) | pad]
#define BB  8       // batch rows per block in K2
#define RB  16      // batch rows per block in K3 (16 = mma n-dim x2)
#define XP  20      // padded row stride (floats) for fp32 XsT (16 rows + 4)
#define OP  17      // padded row stride (floats) for Os
#define WPAD 24     // panel k-stride in halves (conflict-free A-frag LDS)
#define KS_  18     // 288 / 16 k-steps
#define XHS 312     // Xh row stride in halves
#define PANEL_HALVES (GO*WPAD)           // 9216 halves / panel
#define PANEL_U4     (PANEL_HALVES*2/16) // 1152 16B chunks

#define K2_SMEM_BYTES 111952
#define K3_SMEM_FLOATS 24048

// -------- persistent scratch --------
__device__ float g_Eq[V_*E_];
__device__ __align__(16) __half g_Ek[V_*EP];
__device__ __align__(16) __half g_Ev[V_*EP];
__device__ __align__(16) __half g_Pk[T_*EP];
__device__ __align__(16) __half g_Pv[T_*EP];
__device__ float g_pq[E_];
__device__ float g_Gbig[V_*GO];
__device__ __align__(16) __half g_WbigH[KS_*GO*WPAD];
__device__ float g_W2[E_*S2O];
__device__ float g_hg[V_];
__device__ float g_hc1[V_];
__device__ float g_ctx[B_*E_];

__device__ __forceinline__ float dot4(float4 a, float4 b, float s){
    s = fmaf(a.x, b.x, s); s = fmaf(a.y, b.y, s);
    s = fmaf(a.z, b.z, s); s = fmaf(a.w, b.w, s);
    return s;
}
__device__ __forceinline__ float2 h2f(unsigned int u){
    return __half22float2(*reinterpret_cast<const __half2*>(&u));
}
#define FMA2(d,a,b) asm("fma.rn.f32x2 %0, %1, %2, %0;" : "+l"(d) : "l"(a), "l"(b))
#define DUP2(d,f)   asm("mov.b64 %0, {%1, %1};" : "=l"(d) : "f"(f))
#define UNPK(lo,hi,p) asm("mov.b64 {%0, %1}, %2;" : "=f"(lo), "=f"(hi) : "l"(p))

__device__ __forceinline__ void mma16816(float* c, const unsigned* a,
                                         unsigned b0, unsigned b1){
    asm volatile(
        "mma.sync.aligned.m16n8k16.row.col.f32.f16.f16.f32 "
        "{%0,%1,%2,%3}, {%4,%5,%6,%7}, {%8,%9}, {%0,%1,%2,%3};"
        : "+f"(c[0]), "+f"(c[1]), "+f"(c[2]), "+f"(c[3])
        : "r"(a[0]), "r"(a[1]), "r"(a[2]), "r"(a[3]), "r"(b0), "r"(b1));
}
#define CP_ASYNC16(dst,src) \
    asm volatile("cp.async.ca.shared.global [%0], [%1], 16;" :: "r"(dst), "l"(src))
#define CP_COMMIT() asm volatile("cp.async.commit_group;" ::: "memory")
#define CP_WAIT1()  asm volatile("cp.async.wait_group 1;"  ::: "memory")
#define CP_WAIT0()  asm volatile("cp.async.wait_group 0;"  ::: "memory")

__device__ __forceinline__ float gdot96(const float* a, const float* b,
                                        int l, unsigned gmask){
    const float4* a4 = (const float4*)a;
    const float4* b4 = (const float4*)b;
    float s = dot4(a4[l],    b4[l],    0.f);
    s       = dot4(a4[l+8],  b4[l+8],  s);
    s       = dot4(a4[l+16], b4[l+16], s);
    s += __shfl_xor_sync(gmask, s, 4);
    s += __shfl_xor_sync(gmask, s, 2);
    s += __shfl_xor_sync(gmask, s, 1);
    return s;
}

// ================= K1: merged precompute (dot groups + copy tail) =================
#define N_EQ   (V_*E_)
#define N_EK   (V_*E_)
#define N_EV   (V_*E_)
#define N_PK   (T_*E_)
#define N_PV   (T_*E_)
#define N_PQ   (E_)
#define N_GB   (V_*288)
#define N_WA   (E_*288)
#define N_HG   (V_)
#define N_HC   (V_)
#define K1A_GROUPS (N_EQ+N_EK+N_EV+N_PK+N_PV+N_PQ+N_GB+N_WA+N_HG+N_HC)
#define K1A_THREADS (K1A_GROUPS*8)                     // warp-aligned (mod 32 == 0)
#define K1B_TOTAL (V_*E_ + E_*E_ + 192*GO + E_*S2O)
#define K1_TOTAL  (K1A_THREADS + K1B_TOTAL)

__global__ void k1_all(
    const float* __restrict__ tok,  const float* __restrict__ pos,
    const float* __restrict__ ipw,  const float* __restrict__ ipb,
    const float* __restrict__ opw,  const float* __restrict__ opb,
    const float* __restrict__ gih,  const float* __restrict__ ghh,
    const float* __restrict__ gbih, const float* __restrict__ gbhh,
    const float* __restrict__ pgw,  const float* __restrict__ mww,
    const float* __restrict__ lng,  const float* __restrict__ lnb,
    const float* __restrict__ headw,const float* __restrict__ headb)
{
    int gid = blockIdx.x*blockDim.x + threadIdx.x;
    if (gid >= K1_TOTAL) return;

    if (gid < K1A_THREADS){
        int g = gid >> 3;
        const int l = threadIdx.x & 7;
        const unsigned gmask = 0xFFu << (threadIdx.x & 24);

        if (g < N_EQ){
            int v=g/E_, e=g%E_;
            float s = gdot96(tok+v*E_, ipw+e*E_, l, gmask);
            if (!l) g_Eq[v*E_+e] = s;
            return;
        }
        g -= N_EQ;
        if (g < N_EK){
            int v=g/E_, e=g%E_;
            float s = gdot96(tok+v*E_, ipw+(E_+e)*E_, l, gmask);
            if (!l) g_Ek[v*EP+e] = __float2half(s);
            return;
        }
        g -= N_EK;
        if (g < N_EV){
            int v=g/E_, e=g%E_;
            float s = gdot96(tok+v*E_, ipw+(2*E_+e)*E_, l, gmask);
            if (!l) g_Ev[v*EP+e] = __float2half(s);
            return;
        }
        g -= N_EV;
        if (g < N_PK){
            int t=g/E_, e=g%E_;
            float s = gdot96(pos+t*E_, ipw+(E_+e)*E_, l, gmask);
            if (!l) g_Pk[t*EP+e] = __float2half(s + ipb[E_+e]);
            return;
        }
        g -= N_PK;
        if (g < N_PV){
            int t=g/E_, e=g%E_;
            float s = gdot96(pos+t*E_, ipw+(2*E_+e)*E_, l, gmask);
            if (!l) g_Pv[t*EP+e] = __float2half(s + ipb[2*E_+e]);
            return;
        }
        g -= N_PV;
        if (g < N_PQ){
            int e=g;
            float s = gdot96(pos+(T_-1)*E_, ipw+e*E_, l, gmask);
            if (!l) g_pq[e] = s + ipb[e];
            return;
        }
        g -= N_PQ;
        if (g < N_GB){
            int v=g/288, o=g%288;
            float s = gdot96(tok+v*E_, gih+o*288, l, gmask)
                    + gdot96(opb,      gih+o*288+E_, l, gmask);
            if (!l){
                s += gbih[o];
                if (o < 192) s += gbhh[o];
                g_Gbig[v*GO+o] = s;
            }
            return;
        }
        g -= N_GB;
        if (g < N_WA){                      // WbigH k<96, o<288
            int k=g/288, o=g%288;
            const float* gr = gih + o*288 + E_;
            float s = 0.f;
#pragma unroll
            for (int st=0; st<12; st++){
                int j = l + 8*st;
                s = fmaf(gr[j], opw[j*E_+k], s);
            }
            s += __shfl_xor_sync(gmask, s, 4);
            s += __shfl_xor_sync(gmask, s, 2);
            s += __shfl_xor_sync(gmask, s, 1);
            if (!l) g_WbigH[(k>>4)*(GO*WPAD) + o*WPAD + (k&15)] = __float2half(s);
            return;
        }
        g -= N_WA;
        if (g < N_HG){
            float s = gdot96(lng, headw+g*E_, l, gmask);
            if (!l) g_hg[g] = s;
            return;
        }
        g -= N_HG;
        {
            float s = gdot96(lnb, headw+g*E_, l, gmask);
            if (!l) g_hc1[g] = s + headb[g];
        }
        return;
    }

    // ---- copy tail (former k1b) ----
    int i = gid - K1A_THREADS;
    if (i < V_*E_){                         // Gbig o>=288: h_n bias
        int v=i/E_, n=i%E_;
        g_Gbig[v*GO + 288 + n] = gbhh[192+n];
        return;
    }
    i -= V_*E_;
    if (i < E_*E_){                         // WbigH k<96, o>=288: zero
        int k=i/E_, o=288 + i%E_;
        g_WbigH[(k>>4)*(GO*WPAD) + o*WPAD + (k&15)] = __float2half(0.f);
        return;
    }
    i -= E_*E_;
    if (i < 192*GO){                        // WbigH k in [96,288)
        int k = 96 + i/GO, o = i%GO;
        float s = 0.f;
        if (k < 192){
            int m = k - 96;
            if (o < 288) s = gih[o*288 + 2*E_ + m];
        } else {
            int hh = k - 192;
            if (o < 192)       s = ghh[o*E_+hh];
            else if (o >= 288) s = ghh[(192+(o-288))*E_+hh];
        }
        g_WbigH[(k>>4)*(GO*WPAD) + o*WPAD + (k&15)] = __float2half(s);
        return;
    }
    i -= 192*GO;
    if (i < E_*S2O){                        // W2
        int e=i/S2O, o=i%S2O; float s=0.f;
        if (o < 96)       s = mww[o*E_+e];
        else if (o == 96) s = pgw[e];
        else if (o < 195) s = headw[(o-97)*E_+e]*lng[e];
        g_W2[e*S2O+o] = s;
    }
}

// ================================ K2: attention ================================
// SE2 layout: [r][v][6 halves] (12B/record). Score phase hoists 3x u32 gathers
// per r into registers. ctx phase: warp w owns head h=w, lane=(r, col4);
// Pv row loads are warp-uniform per cg (broadcast across r).
__global__ __launch_bounds__(256, 2) void k2_attn(const int* __restrict__ hist)
{
    extern __shared__ char smc[];
    __half* Ek_s = (__half*)smc;                            // 9800 halves
    __half* Pk_s = (__half*)(smc + 19600);                  // 25600 halves
    float*  qh_s = (float*)(smc + 70800);                   // 768 floats
    __half* a_s  = (__half*)(smc + 73872);                  // 12288 halves
    unsigned short* idx_s = (unsigned short*)(smc + 98448); // 2048 u16
    __half* SE2h = (__half*)(smc + 102544);                 // 8*98*6 = 4704 halves

    const int tid = threadIdx.x;
    const int b0  = blockIdx.x * BB;

    for (int i = tid; i < BB*T_; i += 256)
        idx_s[i] = (unsigned short)hist[(b0 + (i>>8))*T_ + (i&255)];
    {
        const uint4* s4 = (const uint4*)g_Ek; uint4* d4 = (uint4*)Ek_s;
        for (int i = tid; i < (V_*EP)/8; i += 256) d4[i] = s4[i];
        const uint4* s5 = (const uint4*)g_Pk; uint4* d5 = (uint4*)Pk_s;
        for (int i = tid; i < (T_*EP)/8; i += 256) d5[i] = s5[i];
    }
    __syncthreads();

    for (int i = tid; i < BB*E_; i += 256) {
        int r = i / E_, e = i % E_;
        int li = idx_s[r*T_ + (T_-1)];
        qh_s[i] = g_Eq[li*E_+e] + g_pq[e];
    }
    __syncthreads();

    // SE phase: SE2[r][v][h] = 0.25 * q[r,h] · Ek[v]
    for (int i = tid; i < H_*V_; i += 256){
        int h = i / V_, v = i % V_;
        const uint2* e2 = (const uint2*)(Ek_s + v*EP + h*HD_);
        uint2 u0=e2[0],u1=e2[1],u2=e2[2],u3=e2[3];
        float2 e0=h2f(u0.x),e1=h2f(u0.y),e2f_=h2f(u1.x),e3=h2f(u1.y);
        float2 e4=h2f(u2.x),e5=h2f(u2.y),e6=h2f(u3.x),e7=h2f(u3.y);
#pragma unroll
        for (int r=0;r<BB;r++){
            const float4* q4 = (const float4*)(qh_s + r*E_ + h*HD_);
            float4 q0=q4[0],q1=q4[1],q2=q4[2],q3=q4[3];
            float s =
              q0.x*e0.x+q0.y*e0.y+q0.z*e1.x+q0.w*e1.y
            + q1.x*e2f_.x+q1.y*e2f_.y+q1.z*e3.x+q1.w*e3.y
            + q2.x*e4.x+q2.y*e4.y+q2.z*e5.x+q2.w*e5.y
            + q3.x*e6.x+q3.y*e6.y+q3.z*e7.x+q3.w*e7.y;
            SE2h[(r*V_+v)*6 + h] = __float2half(s * 0.25f);
        }
    }
    __syncthreads();

    {   // score phase: thread t; SE hoisted per-r into registers
        const int t = tid;
        unsigned rse[BB][3];
#pragma unroll
        for (int r=0;r<BB;r++){
            int ix = idx_s[r*T_+t];
            const __half* p = SE2h + (r*V_ + ix)*6;
            rse[r][0] = *(const unsigned*)(p);               // h0,h1
            rse[r][1] = *(const unsigned*)(p+2);             // h2,h3
            rse[r][2] = *(const unsigned*)(p+4);             // h4,h5
        }
#pragma unroll
        for (int h=0;h<H_;h++){
            const uint2* pk2 = (const uint2*)(Pk_s + t*EP + h*HD_);
            uint2 pu0=pk2[0], pu1=pk2[1], pu2=pk2[2], pu3=pk2[3];
            float2 p0=h2f(pu0.x),p1=h2f(pu0.y),p2=h2f(pu1.x),p3=h2f(pu1.y);
            float2 p4=h2f(pu2.x),p5=h2f(pu2.y),p6=h2f(pu3.x),p7=h2f(pu3.y);
#pragma unroll
            for (int r=0;r<BB;r++){
                const float4* q4 = (const float4*)(qh_s + r*E_ + h*HD_);
                float4 q0=q4[0],q1=q4[1],q2=q4[2],q3=q4[3];
                float d =
                  q0.x*p0.x+q0.y*p0.y+q0.z*p1.x+q0.w*p1.y
                + q1.x*p2.x+q1.y*p2.y+q1.z*p3.x+q1.w*p3.y
                + q2.x*p4.x+q2.y*p4.y+q2.z*p5.x+q2.w*p5.y
                + q3.x*p6.x+q3.y*p6.y+q3.z*p7.x+q3.w*p7.y;
                float2 sp = h2f(rse[r][h>>1]);
                float se = (h&1) ? sp.y : sp.x;
                a_s[(r*H_+h)*T_ + t] = __float2half(fmaf(d, 0.25f, se));
            }
        }
    }
    __syncthreads();

    {   // swap tables to Ev/Pv + warp-per-row softmax
        const uint4* s4 = (const uint4*)g_Ev; uint4* d4 = (uint4*)Ek_s;
        for (int i = tid; i < (V_*EP)/8; i += 256) d4[i] = s4[i];
        const uint4* s5 = (const uint4*)g_Pv; uint4* d5 = (uint4*)Pk_s;
        for (int i = tid; i < (T_*EP)/8; i += 256) d5[i] = s5[i];

        int wid = tid>>5, lane = tid&31;
        int r = wid;
#pragma unroll
        for (int h=0;h<H_;h++){
            __half* row = a_s + (r*H_+h)*T_;
            float v[8]; float m = -1e30f;
#pragma unroll
            for (int j=0;j<8;j++){ v[j]=__half2float(row[lane+32*j]); m = fmaxf(m, v[j]); }
#pragma unroll
            for (int o=16;o;o>>=1) m = fmaxf(m, __shfl_xor_sync(0xffffffffu, m, o));
            float ssum = 0.f;
#pragma unroll
            for (int j=0;j<8;j++){ v[j]=__expf(v[j]-m); ssum += v[j]; }
#pragma unroll
            for (int o=16;o;o>>=1) ssum += __shfl_xor_sync(0xffffffffu, ssum, o);
            float inv = 1.f/ssum;
#pragma unroll
            for (int j=0;j<8;j++) row[lane+32*j] = __float2half(v[j]*inv);
        }
    }
    __syncthreads();

    {   // ctx: warp w = head w; lane = (r, col4); t processed in pairs
        int wid = tid>>5, lane = tid&31;
        if (wid < H_){
            const int r  = lane >> 2;
            const int cg = lane & 3;
            const int col = wid*HD_ + cg*4;
            const __half* arow = a_s + (r*H_+wid)*T_;
            const unsigned short* irow = idx_s + r*T_;
            float ax=0.f, ay=0.f, az=0.f, aw=0.f;
#pragma unroll 2
            for (int j=0;j<T_/2;j++){
                unsigned ixp = *(const unsigned*)(irow + 2*j);
                unsigned avp = *(const unsigned*)(arow + 2*j);
                float2 av = h2f(avp);
                int ix0 = ixp & 0xFFFF, ix1 = ixp >> 16;
                uint2 eu = *(const uint2*)(Ek_s + ix0*EP + col);   // Ev now
                uint2 pu = *(const uint2*)(Pk_s + (2*j)*EP + col); // Pv now
                float2 e0=h2f(eu.x), e1=h2f(eu.y), p0=h2f(pu.x), p1=h2f(pu.y);
                ax += av.x*(e0.x+p0.x); ay += av.x*(e0.y+p0.y);
                az += av.x*(e1.x+p1.x); aw += av.x*(e1.y+p1.y);
                eu = *(const uint2*)(Ek_s + ix1*EP + col);
                pu = *(const uint2*)(Pk_s + (2*j+1)*EP + col);
                e0=h2f(eu.x); e1=h2f(eu.y); p0=h2f(pu.x); p1=h2f(pu.y);
                ax += av.y*(e0.x+p0.x); ay += av.y*(e0.y+p0.y);
                az += av.y*(e1.x+p1.x); aw += av.y*(e1.y+p1.y);
            }
            *(float4*)(g_ctx + (b0+r)*E_ + col) = make_float4(ax,ay,az,aw);
        }
    }
}

// ==================== K3: tensor-core GRU + memory gate + LN + head ====================
__global__ __launch_bounds__(256, 2) void k3_gru(
    const int* __restrict__ cidx, const float* __restrict__ hidden,
    const float* __restrict__ memory, const float* __restrict__ mwb,
    const float* __restrict__ pgb,
    float* __restrict__ out_logits, float* __restrict__ out_hidden,
    float* __restrict__ out_memory)
{
    extern __shared__ float sm[];
    float*  XsT  = sm;                       // 288*XP = 5760 f
    __half* Xh   = (__half*)(sm + 5760);     // 16*XHS = 4992 halves
    __half* WP   = (__half*)(sm + 8256);     // 2 panels x 9216 halves
    float*  Os   = sm + 17472;               // 384*OP = 6528 f
    float*  mu_s = sm + 24000;
    float*  rs_s = sm + 24016;
    int*    cidx_s = (int*)(sm + 24032);

    const int tid = threadIdx.x;
    const int b0  = blockIdx.x * RB;
    const int wid = tid>>5, lane = tid&31;
    const int gq  = lane>>2, tq = lane&3;

    const unsigned wp_u32 = (unsigned)__cvta_generic_to_shared(WP);
    {
        const char* src = (const char*)g_WbigH;
#pragma unroll
        for (int j = 0; j < 5; j++){
            int idx = tid + j*256;
            if (idx < PANEL_U4) CP_ASYNC16(wp_u32 + idx*16, src + idx*16);
        }
        CP_COMMIT();
    }

    if (tid < RB) cidx_s[tid] = cidx[b0+tid];
    for (int i = tid; i < RB*E_; i += 256){
        int r = i/E_, c = i%E_;
        float cv = g_ctx[(b0+r)*E_ + c];
        float mv = memory[(b0+r)*E_ + c];
        float hv = hidden[(b0+r)*E_ + c];
        XsT[c*XP + r]        = cv;
        XsT[(E_+c)*XP + r]   = mv;
        XsT[(2*E_+c)*XP + r] = hv;
        Xh[r*XHS + c]        = __float2half(cv);
        Xh[r*XHS + E_ + c]   = __float2half(mv);
        Xh[r*XHS + 2*E_ + c] = __float2half(hv);
    }
    __syncthreads();

    float acc[3][2][4];
#pragma unroll
    for (int i=0;i<3;i++)
#pragma unroll
        for (int n=0;n<2;n++)
#pragma unroll
            for (int j=0;j<4;j++) acc[i][n][j] = 0.f;

    for (int ks = 0; ks < KS_; ks++){
        if (ks < KS_-1){
            const char* src = (const char*)(g_WbigH + (ks+1)*PANEL_HALVES);
            unsigned dst = wp_u32 + ((ks+1)&1)*(PANEL_HALVES*2);
#pragma unroll
            for (int j = 0; j < 5; j++){
                int idx = tid + j*256;
                if (idx < PANEL_U4) CP_ASYNC16(dst + idx*16, src + idx*16);
            }
            CP_COMMIT();
            CP_WAIT1();
        } else {
            CP_WAIT0();
        }
        __syncthreads();

        const __half* wp = WP + (ks&1)*PANEL_HALVES;
        unsigned b0n0 = *(const unsigned*)(Xh + gq*XHS     + ks*16 + 2*tq);
        unsigned b1n0 = *(const unsigned*)(Xh + gq*XHS     + ks*16 + 2*tq + 8);
        unsigned b0n1 = *(const unsigned*)(Xh + (gq+8)*XHS + ks*16 + 2*tq);
        unsigned b1n1 = *(const unsigned*)(Xh + (gq+8)*XHS + ks*16 + 2*tq + 8);
#pragma unroll
        for (int i=0;i<3;i++){
            int ob = (wid + 8*i)*16;
            unsigned a[4];
            a[0] = *(const unsigned*)(wp + (ob+gq)*WPAD   + 2*tq);
            a[1] = *(const unsigned*)(wp + (ob+gq+8)*WPAD + 2*tq);
            a[2] = *(const unsigned*)(wp + (ob+gq)*WPAD   + 2*tq + 8);
            a[3] = *(const unsigned*)(wp + (ob+gq+8)*WPAD + 2*tq + 8);
            mma16816(acc[i][0], a, b0n0, b1n0);
            mma16816(acc[i][1], a, b0n1, b1n1);
        }
        __syncthreads();
    }

    {
        const float* gb = g_Gbig;
#pragma unroll
        for (int i=0;i<3;i++){
            int o_lo = (wid + 8*i)*16 + gq;
            int o_hi = o_lo + 8;
#pragma unroll
            for (int nt=0;nt<2;nt++){
                int r0 = nt*8 + 2*tq, r1 = r0 + 1;
                Os[o_lo*OP + r0] = acc[i][nt][0] + gb[cidx_s[r0]*GO + o_lo];
                Os[o_lo*OP + r1] = acc[i][nt][1] + gb[cidx_s[r1]*GO + o_lo];
                Os[o_hi*OP + r0] = acc[i][nt][2] + gb[cidx_s[r0]*GO + o_hi];
                Os[o_hi*OP + r1] = acc[i][nt][3] + gb[cidx_s[r1]*GO + o_hi];
            }
        }
    }
    __syncthreads();

    for (int i = tid; i < RB*E_; i += 256){
        int r = i/E_, e = i%E_;
        float orv = Os[e*OP+r];
        float ozv = Os[(E_+e)*OP+r];
        float oin = Os[(2*E_+e)*OP+r];
        float ohn = Os[(3*E_+e)*OP+r];
        float rr = 1.f/(1.f+__expf(-orv));
        float zz = 1.f/(1.f+__expf(-ozv));
        float nn = tanhf(oin + rr*ohn);
        float hp = XsT[(2*E_+e)*XP + r];
        float nh = (1.f-zz)*nn + zz*hp;
        XsT[e*XP + r] = nh;
        out_hidden[(b0+r)*E_ + e] = nh;
    }
    __syncthreads();

    {
        int r = tid>>4, l16 = tid&15;
        float s=0.f, sq=0.f;
#pragma unroll
        for (int e=l16; e<E_; e+=16){ float v = XsT[e*XP+r]; s += v; sq += v*v; }
#pragma unroll
        for (int o=8;o;o>>=1){
            s  += __shfl_xor_sync(0xffffffffu, s,  o);
            sq += __shfl_xor_sync(0xffffffffu, sq, o);
        }
        if (l16==0){
            float mu = s*(1.f/E_);
            float var = sq*(1.f/E_) - mu*mu;
            mu_s[r] = mu;
            rs_s[r] = rsqrtf(var + 1e-5f);
        }
    }
    __syncthreads();

    if (wid < 4){
        const int o0 = wid*64 + lane*2;
        if (o0 < S2O){
            unsigned long long accA[8], accB[8];
#pragma unroll
            for (int j=0;j<8;j++){ accA[j]=0ull; accB[j]=0ull; }
#pragma unroll 4
            for (int k=0;k<E_;k++){
                float2 wp2 = *(const float2*)(g_W2 + k*S2O + o0);
                unsigned long long wa, wb;
                DUP2(wa, wp2.x); DUP2(wb, wp2.y);
                const ulonglong2* xr = (const ulonglong2*)(XsT + k*XP);
                ulonglong2 x0 = xr[0], x1 = xr[1], x2 = xr[2], x3 = xr[3];
                FMA2(accA[0], x0.x, wa); FMA2(accA[1], x0.y, wa);
                FMA2(accA[2], x1.x, wa); FMA2(accA[3], x1.y, wa);
                FMA2(accA[4], x2.x, wa); FMA2(accA[5], x2.y, wa);
                FMA2(accA[6], x3.x, wa); FMA2(accA[7], x3.y, wa);
                FMA2(accB[0], x0.x, wb); FMA2(accB[1], x0.y, wb);
                FMA2(accB[2], x1.x, wb); FMA2(accB[3], x1.y, wb);
                FMA2(accB[4], x2.x, wb); FMA2(accB[5], x2.y, wb);
                FMA2(accB[6], x3.x, wb); FMA2(accB[7], x3.y, wb);
            }
#pragma unroll
            for (int j=0;j<8;j++){
                float lo, hi;
                UNPK(lo, hi, accA[j]);
                Os[o0*OP + 2*j]       = lo;
                Os[o0*OP + 2*j+1]     = hi;
                UNPK(lo, hi, accB[j]);
                Os[(o0+1)*OP + 2*j]   = lo;
                Os[(o0+1)*OP + 2*j+1] = hi;
            }
        }
    }
    __syncthreads();

    float pgb0 = pgb[0];
    for (int i = tid; i < RB*E_; i += 256){
        int r = i/E_, e = i%E_;
        float p    = 1.f/(1.f+__expf(-(Os[96*OP+r] + pgb0)));
        float cand = tanhf(Os[e*OP+r] + mwb[e]);
        float mem  = XsT[(E_+e)*XP + r];
        out_memory[(b0+r)*E_ + e] = (1.f-p)*mem + p*cand;
    }
    for (int i = tid; i < RB*V_; i += 256){
        int r = i/V_, v = i%V_;
        float y = Os[(97+v)*OP + r];
        out_logits[(b0+r)*V_ + v] = rs_s[r]*(y - mu_s[r]*g_hg[v]) + g_hc1[v];
    }
}

// ================================== launch ==================================
extern "C" void kernel_launch(void* const* d_in, const int* in_sizes, int n_in,
                              void* d_out, int out_size)
{
    const int*   cidx = (const int*)  d_in[0];
    const int*   hist = (const int*)  d_in[1];
    const float* hid  = (const float*)d_in[2];
    const float* mem  = (const float*)d_in[3];
    const float* tok  = (const float*)d_in[4];
    const float* pos  = (const float*)d_in[5];
    const float* ipw  = (const float*)d_in[6];
    const float* ipb  = (const float*)d_in[7];
    const float* opw  = (const float*)d_in[8];
    const float* opb  = (const float*)d_in[9];
    const float* gih  = (const float*)d_in[10];
    const float* ghh  = (const float*)d_in[11];
    const float* gbih = (const float*)d_in[12];
    const float* gbhh = (const float*)d_in[13];
    const float* pgw  = (const float*)d_in[14];
    const float* pgb  = (const float*)d_in[15];
    const float* mww  = (const float*)d_in[16];
    const float* mwb  = (const float*)d_in[17];
    const float* lng  = (const float*)d_in[18];
    const float* lnb  = (const float*)d_in[19];
    const float* hdw  = (const float*)d_in[20];
    const float* hdb  = (const float*)d_in[21];

    float* out         = (float*)d_out;
    float* out_logits  = out;
    float* out_hidden  = out + (size_t)B_*V_;
    float* out_memory  = out + (size_t)B_*V_ + (size_t)B_*E_;

    cudaFuncSetAttribute(k2_attn, cudaFuncAttributeMaxDynamicSharedMemorySize,
                         K2_SMEM_BYTES);
    cudaFuncSetAttribute(k3_gru,  cudaFuncAttributeMaxDynamicSharedMemorySize,
                         K3_SMEM_FLOATS*4);

    k1_all<<<(K1_TOTAL + 255)/256, 256>>>(tok,pos,ipw,ipb,opw,opb,
                                          gih,ghh,gbih,gbhh,pgw,mww,
                                          lng,lnb,hdw,hdb);
    k2_attn<<<B_/BB, 256, K2_SMEM_BYTES>>>(hist);
    k3_gru <<<B_/RB, 256, K3_SMEM_FLOATS*4>>>(cidx, hid, mem, mwb, pgb,
                                              out_logits, out_hidden, out_memory);
}

// round 17
// speedup vs baseline: 1.0702x; 1.0702x over previous
#include <cuda_runtime.h>
#include <cuda_fp16.h>
#include <cuda_bf16.h>
#include <math.h>

#define B_  4096
#define T_  256
#define E_  96
#define H_  6
#define HD_ 16
#define V_  98
#define EP  100     // padded row stride (halves) for Ek/Ev/Pk/Pv tables
#define GO  384     // stage-1 fused outputs: [r|z (192) | i_n (96) | h_n (96)]
#define S2O 224     // stage-2 padded outputs: [cand(96) | p(1) | head(98) | pad]
#define BB  8       // batch rows per block in K2
#define RB  16      // batch rows per block in K3 (16 = mma n-dim x2)
#define XP  20      // padded row stride (floats) for fp32 XsT (16 rows + 4)
#define OP  17      // padded row stride (floats) for Os
#define WPAD 24     // panel k-stride in halves (conflict-free A-frag LDS)
#define KS_  18     // 288 / 16 k-steps
#define XHS 312     // Xh row stride in halves
#define PANEL_HALVES (GO*WPAD)           // 9216 halves / panel
#define PANEL_U4     (PANEL_HALVES*2/16) // 1152 16B chunks

#define K2_SMEM_BYTES 111952
#define K3_SMEM_FLOATS 24048

// -------- persistent scratch --------
__device__ float g_Eq[V_*E_];
__device__ __align__(16) __half g_Ek[V_*EP];
__device__ __align__(16) __half g_Ev[V_*EP];
__device__ __align__(16) __half g_Pk[T_*EP];
__device__ __align__(16) __half g_Pv[T_*EP];
__device__ float g_pq[E_];
__device__ float g_Gbig[V_*GO];
__device__ __align__(16) __half g_WbigH[KS_*GO*WPAD];
__device__ float g_W2[E_*S2O];
__device__ float g_hg[V_];
__device__ float g_hc1[V_];
__device__ float g_ctx[B_*E_];

__device__ __forceinline__ float dot4(float4 a, float4 b, float s){
    s = fmaf(a.x, b.x, s); s = fmaf(a.y, b.y, s);
    s = fmaf(a.z, b.z, s); s = fmaf(a.w, b.w, s);
    return s;
}
__device__ __forceinline__ float2 h2f(unsigned int u){
    return __half22float2(*reinterpret_cast<const __half2*>(&u));
}
#define FMA2(d,a,b) asm("fma.rn.f32x2 %0, %1, %2, %0;" : "+l"(d) : "l"(a), "l"(b))
#define DUP2(d,f)   asm("mov.b64 %0, {%1, %1};" : "=l"(d) : "f"(f))
#define UNPK(lo,hi,p) asm("mov.b64 {%0, %1}, %2;" : "=f"(lo), "=f"(hi) : "l"(p))

__device__ __forceinline__ void mma16816(float* c, const unsigned* a,
                                         unsigned b0, unsigned b1){
    asm volatile(
        "mma.sync.aligned.m16n8k16.row.col.f32.f16.f16.f32 "
        "{%0,%1,%2,%3}, {%4,%5,%6,%7}, {%8,%9}, {%0,%1,%2,%3};"
        : "+f"(c[0]), "+f"(c[1]), "+f"(c[2]), "+f"(c[3])
        : "r"(a[0]), "r"(a[1]), "r"(a[2]), "r"(a[3]), "r"(b0), "r"(b1));
}
#define CP_ASYNC16(dst,src) \
    asm volatile("cp.async.ca.shared.global [%0], [%1], 16;" :: "r"(dst), "l"(src))
#define CP_COMMIT() asm volatile("cp.async.commit_group;" ::: "memory")
#define CP_WAIT1()  asm volatile("cp.async.wait_group 1;"  ::: "memory")
#define CP_WAIT0()  asm volatile("cp.async.wait_group 0;"  ::: "memory")

__device__ __forceinline__ float gdot96(const float* a, const float* b,
                                        int l, unsigned gmask){
    const float4* a4 = (const float4*)a;
    const float4* b4 = (const float4*)b;
    float s = dot4(a4[l],    b4[l],    0.f);
    s       = dot4(a4[l+8],  b4[l+8],  s);
    s       = dot4(a4[l+16], b4[l+16], s);
    s += __shfl_xor_sync(gmask, s, 4);
    s += __shfl_xor_sync(gmask, s, 2);
    s += __shfl_xor_sync(gmask, s, 1);
    return s;
}

// ================= K1: merged precompute (dot groups + copy tail) =================
#define N_EQ   (V_*E_)
#define N_EK   (V_*E_)
#define N_EV   (V_*E_)
#define N_PK   (T_*E_)
#define N_PV   (T_*E_)
#define N_PQ   (E_)
#define N_GB   (V_*288)
#define N_WA   (E_*288)
#define N_HG   (V_)
#define N_HC   (V_)
#define K1A_GROUPS (N_EQ+N_EK+N_EV+N_PK+N_PV+N_PQ+N_GB+N_WA+N_HG+N_HC)
#define K1A_THREADS (K1A_GROUPS*8)
#define K1B_TOTAL (V_*E_ + E_*E_ + 192*GO + E_*S2O)
#define K1_TOTAL  (K1A_THREADS + K1B_TOTAL)

__global__ void k1_all(
    const float* __restrict__ tok,  const float* __restrict__ pos,
    const float* __restrict__ ipw,  const float* __restrict__ ipb,
    const float* __restrict__ opw,  const float* __restrict__ opb,
    const float* __restrict__ gih,  const float* __restrict__ ghh,
    const float* __restrict__ gbih, const float* __restrict__ gbhh,
    const float* __restrict__ pgw,  const float* __restrict__ mww,
    const float* __restrict__ lng,  const float* __restrict__ lnb,
    const float* __restrict__ headw,const float* __restrict__ headb)
{
    int gid = blockIdx.x*blockDim.x + threadIdx.x;
    if (gid >= K1_TOTAL) return;

    if (gid < K1A_THREADS){
        int g = gid >> 3;
        const int l = threadIdx.x & 7;
        const unsigned gmask = 0xFFu << (threadIdx.x & 24);

        if (g < N_EQ){
            int v=g/E_, e=g%E_;
            float s = gdot96(tok+v*E_, ipw+e*E_, l, gmask);
            if (!l) g_Eq[v*E_+e] = s;
            return;
        }
        g -= N_EQ;
        if (g < N_EK){
            int v=g/E_, e=g%E_;
            float s = gdot96(tok+v*E_, ipw+(E_+e)*E_, l, gmask);
            if (!l) g_Ek[v*EP+e] = __float2half(s);
            return;
        }
        g -= N_EK;
        if (g < N_EV){
            int v=g/E_, e=g%E_;
            float s = gdot96(tok+v*E_, ipw+(2*E_+e)*E_, l, gmask);
            if (!l) g_Ev[v*EP+e] = __float2half(s);
            return;
        }
        g -= N_EV;
        if (g < N_PK){
            int t=g/E_, e=g%E_;
            float s = gdot96(pos+t*E_, ipw+(E_+e)*E_, l, gmask);
            if (!l) g_Pk[t*EP+e] = __float2half(s + ipb[E_+e]);
            return;
        }
        g -= N_PK;
        if (g < N_PV){
            int t=g/E_, e=g%E_;
            float s = gdot96(pos+t*E_, ipw+(2*E_+e)*E_, l, gmask);
            if (!l) g_Pv[t*EP+e] = __float2half(s + ipb[2*E_+e]);
            return;
        }
        g -= N_PV;
        if (g < N_PQ){
            int e=g;
            float s = gdot96(pos+(T_-1)*E_, ipw+e*E_, l, gmask);
            if (!l) g_pq[e] = s + ipb[e];
            return;
        }
        g -= N_PQ;
        if (g < N_GB){
            int v=g/288, o=g%288;
            float s = gdot96(tok+v*E_, gih+o*288, l, gmask)
                    + gdot96(opb,      gih+o*288+E_, l, gmask);
            if (!l){
                s += gbih[o];
                if (o < 192) s += gbhh[o];
                g_Gbig[v*GO+o] = s;
            }
            return;
        }
        g -= N_GB;
        if (g < N_WA){                      // WbigH k<96, o<288
            int k=g/288, o=g%288;
            const float* gr = gih + o*288 + E_;
            float s = 0.f;
#pragma unroll
            for (int st=0; st<12; st++){
                int j = l + 8*st;
                s = fmaf(gr[j], opw[j*E_+k], s);
            }
            s += __shfl_xor_sync(gmask, s, 4);
            s += __shfl_xor_sync(gmask, s, 2);
            s += __shfl_xor_sync(gmask, s, 1);
            if (!l) g_WbigH[(k>>4)*(GO*WPAD) + o*WPAD + (k&15)] = __float2half(s);
            return;
        }
        g -= N_WA;
        if (g < N_HG){
            float s = gdot96(lng, headw+g*E_, l, gmask);
            if (!l) g_hg[g] = s;
            return;
        }
        g -= N_HG;
        {
            float s = gdot96(lnb, headw+g*E_, l, gmask);
            if (!l) g_hc1[g] = s + headb[g];
        }
        return;
    }

    // ---- copy tail ----
    int i = gid - K1A_THREADS;
    if (i < V_*E_){                         // Gbig o>=288: h_n bias
        int v=i/E_, n=i%E_;
        g_Gbig[v*GO + 288 + n] = gbhh[192+n];
        return;
    }
    i -= V_*E_;
    if (i < E_*E_){                         // WbigH k<96, o>=288: zero
        int k=i/E_, o=288 + i%E_;
        g_WbigH[(k>>4)*(GO*WPAD) + o*WPAD + (k&15)] = __float2half(0.f);
        return;
    }
    i -= E_*E_;
    if (i < 192*GO){                        // WbigH k in [96,288)
        int k = 96 + i/GO, o = i%GO;
        float s = 0.f;
        if (k < 192){
            int m = k - 96;
            if (o < 288) s = gih[o*288 + 2*E_ + m];
        } else {
            int hh = k - 192;
            if (o < 192)       s = ghh[o*E_+hh];
            else if (o >= 288) s = ghh[(192+(o-288))*E_+hh];
        }
        g_WbigH[(k>>4)*(GO*WPAD) + o*WPAD + (k&15)] = __float2half(s);
        return;
    }
    i -= 192*GO;
    if (i < E_*S2O){                        // W2
        int e=i/S2O, o=i%S2O; float s=0.f;
        if (o < 96)       s = mww[o*E_+e];
        else if (o == 96) s = pgw[e];
        else if (o < 195) s = headw[(o-97)*E_+e]*lng[e];
        g_W2[e*S2O+o] = s;
    }
}

// ================================ K2: attention (R13 version) ================================
__global__ __launch_bounds__(256, 2) void k2_attn(const int* __restrict__ hist)
{
    extern __shared__ char smc[];
    __half* Ek_s = (__half*)smc;                            // 9800 halves
    __half* Pk_s = (__half*)(smc + 19600);                  // 25600 halves
    float*  qh_s = (float*)(smc + 70800);                   // 768 floats
    __half* a_s  = (__half*)(smc + 73872);                  // 12288 halves
    unsigned short* idx_s = (unsigned short*)(smc + 98448); // 2048 u16
    __half* SE_s = (__half*)(smc + 102544);                 // 48*98 = 4704 halves

    const int tid = threadIdx.x;
    const int b0  = blockIdx.x * BB;

    for (int i = tid; i < BB*T_; i += 256)
        idx_s[i] = (unsigned short)hist[(b0 + (i>>8))*T_ + (i&255)];
    {
        const uint4* s4 = (const uint4*)g_Ek; uint4* d4 = (uint4*)Ek_s;
        for (int i = tid; i < (V_*EP)/8; i += 256) d4[i] = s4[i];
        const uint4* s5 = (const uint4*)g_Pk; uint4* d5 = (uint4*)Pk_s;
        for (int i = tid; i < (T_*EP)/8; i += 256) d5[i] = s5[i];
    }
    __syncthreads();

    for (int i = tid; i < BB*E_; i += 256) {
        int r = i / E_, e = i % E_;
        int li = idx_s[r*T_ + (T_-1)];
        qh_s[i] = g_Eq[li*E_+e] + g_pq[e];
    }
    __syncthreads();

    // SE phase: SE[r,h,v] = 0.25 * q[r,h] · Ek[v]
    for (int i = tid; i < H_*V_; i += 256){
        int h = i / V_, v = i % V_;
        const uint2* e2 = (const uint2*)(Ek_s + v*EP + h*HD_);
        uint2 u0=e2[0],u1=e2[1],u2=e2[2],u3=e2[3];
        float2 e0=h2f(u0.x),e1=h2f(u0.y),e2f_=h2f(u1.x),e3=h2f(u1.y);
        float2 e4=h2f(u2.x),e5=h2f(u2.y),e6=h2f(u3.x),e7=h2f(u3.y);
#pragma unroll
        for (int r=0;r<BB;r++){
            const float4* q4 = (const float4*)(qh_s + r*E_ + h*HD_);
            float4 q0=q4[0],q1=q4[1],q2=q4[2],q3=q4[3];
            float s =
              q0.x*e0.x+q0.y*e0.y+q0.z*e1.x+q0.w*e1.y
            + q1.x*e2f_.x+q1.y*e2f_.y+q1.z*e3.x+q1.w*e3.y
            + q2.x*e4.x+q2.y*e4.y+q2.z*e5.x+q2.w*e5.y
            + q3.x*e6.x+q3.y*e6.y+q3.z*e7.x+q3.w*e7.y;
            SE_s[(r*H_+h)*V_ + v] = __float2half(s * 0.25f);
        }
    }
    __syncthreads();

    {   // score phase: thread t; lazy per-(h,r) SE gather
        const int t = tid;
        int myidx[BB];
#pragma unroll
        for (int r=0;r<BB;r++) myidx[r] = idx_s[r*T_+t];
#pragma unroll
        for (int h=0;h<H_;h++){
            const uint2* pk2 = (const uint2*)(Pk_s + t*EP + h*HD_);
            uint2 pu0=pk2[0], pu1=pk2[1], pu2=pk2[2], pu3=pk2[3];
            float2 p0=h2f(pu0.x),p1=h2f(pu0.y),p2=h2f(pu1.x),p3=h2f(pu1.y);
            float2 p4=h2f(pu2.x),p5=h2f(pu2.y),p6=h2f(pu3.x),p7=h2f(pu3.y);
#pragma unroll
            for (int r=0;r<BB;r++){
                const float4* q4 = (const float4*)(qh_s + r*E_ + h*HD_);
                float4 q0=q4[0],q1=q4[1],q2=q4[2],q3=q4[3];
                float d =
                  q0.x*p0.x+q0.y*p0.y+q0.z*p1.x+q0.w*p1.y
                + q1.x*p2.x+q1.y*p2.y+q1.z*p3.x+q1.w*p3.y
                + q2.x*p4.x+q2.y*p4.y+q2.z*p5.x+q2.w*p5.y
                + q3.x*p6.x+q3.y*p6.y+q3.z*p7.x+q3.w*p7.y;
                float se = __half2float(SE_s[(r*H_+h)*V_ + myidx[r]]);
                a_s[(r*H_+h)*T_ + t] = __float2half(fmaf(d, 0.25f, se));
            }
        }
    }
    __syncthreads();

    {   // swap tables to Ev/Pv + warp-per-row softmax
        const uint4* s4 = (const uint4*)g_Ev; uint4* d4 = (uint4*)Ek_s;
        for (int i = tid; i < (V_*EP)/8; i += 256) d4[i] = s4[i];
        const uint4* s5 = (const uint4*)g_Pv; uint4* d5 = (uint4*)Pk_s;
        for (int i = tid; i < (T_*EP)/8; i += 256) d5[i] = s5[i];

        int wid = tid>>5, lane = tid&31;
        int r = wid;
#pragma unroll
        for (int h=0;h<H_;h++){
            __half* row = a_s + (r*H_+h)*T_;
            float v[8]; float m = -1e30f;
#pragma unroll
            for (int j=0;j<8;j++){ v[j]=__half2float(row[lane+32*j]); m = fmaxf(m, v[j]); }
#pragma unroll
            for (int o=16;o;o>>=1) m = fmaxf(m, __shfl_xor_sync(0xffffffffu, m, o));
            float ssum = 0.f;
#pragma unroll
            for (int j=0;j<8;j++){ v[j]=__expf(v[j]-m); ssum += v[j]; }
#pragma unroll
            for (int o=16;o;o>>=1) ssum += __shfl_xor_sync(0xffffffffu, ssum, o);
            float inv = 1.f/ssum;
#pragma unroll
            for (int j=0;j<8;j++) row[lane+32*j] = __float2half(v[j]*inv);
        }
    }
    __syncthreads();

    if (tid < BB*24) {                      // ctx: thread = (row, 4-wide col group)
        int r = tid/24, g = tid%24;
        int h = g>>2, col = g*4;
        const __half* arow = a_s + (r*H_+h)*T_;
        const unsigned short* irow = idx_s + r*T_;
        float ax=0.f, ay=0.f, az=0.f, aw=0.f;
#pragma unroll 4
        for (int t2=0;t2<T_;t2++){
            float av = __half2float(arow[t2]);
            int   ix = irow[t2];
            uint2 eu = *(const uint2*)(Ek_s + ix*EP + col);   // holds Ev now
            uint2 pu = *(const uint2*)(Pk_s + t2*EP + col);   // holds Pv now
            float2 e0=h2f(eu.x), e1=h2f(eu.y), p0=h2f(pu.x), p1=h2f(pu.y);
            ax += av*(e0.x+p0.x); ay += av*(e0.y+p0.y);
            az += av*(e1.x+p1.x); aw += av*(e1.y+p1.y);
        }
        *(float4*)(g_ctx + (b0+r)*E_ + col) = make_float4(ax,ay,az,aw);
    }
}

// ==================== K3: tensor-core GRU + memory gate + LN + head ====================
__global__ __launch_bounds__(256, 2) void k3_gru(
    const int* __restrict__ cidx, const float* __restrict__ hidden,
    const float* __restrict__ memory, const float* __restrict__ mwb,
    const float* __restrict__ pgb,
    float* __restrict__ out_logits, float* __restrict__ out_hidden,
    float* __restrict__ out_memory)
{
    extern __shared__ float sm[];
    float*  XsT  = sm;                       // 288*XP = 5760 f
    __half* Xh   = (__half*)(sm + 5760);     // 16*XHS = 4992 halves
    __half* WP   = (__half*)(sm + 8256);     // 2 panels x 9216 halves
    float*  Os   = sm + 17472;               // 384*OP = 6528 f
    float*  mu_s = sm + 24000;
    float*  rs_s = sm + 24016;
    int*    cidx_s = (int*)(sm + 24032);

    const int tid = threadIdx.x;
    const int b0  = blockIdx.x * RB;
    const int wid = tid>>5, lane = tid&31;
    const int gq  = lane>>2, tq = lane&3;

    const unsigned wp_u32 = (unsigned)__cvta_generic_to_shared(WP);
    {
        const char* src = (const char*)g_WbigH;
#pragma unroll
        for (int j = 0; j < 5; j++){
            int idx = tid + j*256;
            if (idx < PANEL_U4) CP_ASYNC16(wp_u32 + idx*16, src + idx*16);
        }
        CP_COMMIT();
    }

    if (tid < RB) cidx_s[tid] = cidx[b0+tid];
    for (int i = tid; i < RB*E_; i += 256){
        int r = i/E_, c = i%E_;
        float cv = g_ctx[(b0+r)*E_ + c];
        float mv = memory[(b0+r)*E_ + c];
        float hv = hidden[(b0+r)*E_ + c];
        XsT[c*XP + r]        = cv;
        XsT[(E_+c)*XP + r]   = mv;
        XsT[(2*E_+c)*XP + r] = hv;
        Xh[r*XHS + c]        = __float2half(cv);
        Xh[r*XHS + E_ + c]   = __float2half(mv);
        Xh[r*XHS + 2*E_ + c] = __float2half(hv);
    }
    __syncthreads();

    float acc[3][2][4];
#pragma unroll
    for (int i=0;i<3;i++)
#pragma unroll
        for (int n=0;n<2;n++)
#pragma unroll
            for (int j=0;j<4;j++) acc[i][n][j] = 0.f;

    for (int ks = 0; ks < KS_; ks++){
        if (ks < KS_-1){
            const char* src = (const char*)(g_WbigH + (ks+1)*PANEL_HALVES);
            unsigned dst = wp_u32 + ((ks+1)&1)*(PANEL_HALVES*2);
#pragma unroll
            for (int j = 0; j < 5; j++){
                int idx = tid + j*256;
                if (idx < PANEL_U4) CP_ASYNC16(dst + idx*16, src + idx*16);
            }
            CP_COMMIT();
            CP_WAIT1();
        } else {
            CP_WAIT0();
        }
        __syncthreads();

        const __half* wp = WP + (ks&1)*PANEL_HALVES;
        unsigned b0n0 = *(const unsigned*)(Xh + gq*XHS     + ks*16 + 2*tq);
        unsigned b1n0 = *(const unsigned*)(Xh + gq*XHS     + ks*16 + 2*tq + 8);
        unsigned b0n1 = *(const unsigned*)(Xh + (gq+8)*XHS + ks*16 + 2*tq);
        unsigned b1n1 = *(const unsigned*)(Xh + (gq+8)*XHS + ks*16 + 2*tq + 8);
#pragma unroll
        for (int i=0;i<3;i++){
            int ob = (wid + 8*i)*16;
            unsigned a[4];
            a[0] = *(const unsigned*)(wp + (ob+gq)*WPAD   + 2*tq);
            a[1] = *(const unsigned*)(wp + (ob+gq+8)*WPAD + 2*tq);
            a[2] = *(const unsigned*)(wp + (ob+gq)*WPAD   + 2*tq + 8);
            a[3] = *(const unsigned*)(wp + (ob+gq+8)*WPAD + 2*tq + 8);
            mma16816(acc[i][0], a, b0n0, b1n0);
            mma16816(acc[i][1], a, b0n1, b1n1);
        }
        __syncthreads();
    }

    {
        const float* gb = g_Gbig;
#pragma unroll
        for (int i=0;i<3;i++){
            int o_lo = (wid + 8*i)*16 + gq;
            int o_hi = o_lo + 8;
#pragma unroll
            for (int nt=0;nt<2;nt++){
                int r0 = nt*8 + 2*tq, r1 = r0 + 1;
                Os[o_lo*OP + r0] = acc[i][nt][0] + gb[cidx_s[r0]*GO + o_lo];
                Os[o_lo*OP + r1] = acc[i][nt][1] + gb[cidx_s[r1]*GO + o_lo];
                Os[o_hi*OP + r0] = acc[i][nt][2] + gb[cidx_s[r0]*GO + o_hi];
                Os[o_hi*OP + r1] = acc[i][nt][3] + gb[cidx_s[r1]*GO + o_hi];
            }
        }
    }
    __syncthreads();

    for (int i = tid; i < RB*E_; i += 256){
        int r = i/E_, e = i%E_;
        float orv = Os[e*OP+r];
        float ozv = Os[(E_+e)*OP+r];
        float oin = Os[(2*E_+e)*OP+r];
        float ohn = Os[(3*E_+e)*OP+r];
        float rr = 1.f/(1.f+__expf(-orv));
        float zz = 1.f/(1.f+__expf(-ozv));
        float nn = tanhf(oin + rr*ohn);
        float hp = XsT[(2*E_+e)*XP + r];
        float nh = (1.f-zz)*nn + zz*hp;
        XsT[e*XP + r] = nh;
        out_hidden[(b0+r)*E_ + e] = nh;
    }
    __syncthreads();

    {
        int r = tid>>4, l16 = tid&15;
        float s=0.f, sq=0.f;
#pragma unroll
        for (int e=l16; e<E_; e+=16){ float v = XsT[e*XP+r]; s += v; sq += v*v; }
#pragma unroll
        for (int o=8;o;o>>=1){
            s  += __shfl_xor_sync(0xffffffffu, s,  o);
            sq += __shfl_xor_sync(0xffffffffu, sq, o);
        }
        if (l16==0){
            float mu = s*(1.f/E_);
            float var = sq*(1.f/E_) - mu*mu;
            mu_s[r] = mu;
            rs_s[r] = rsqrtf(var + 1e-5f);
        }
    }
    __syncthreads();

    if (wid < 4){
        const int o0 = wid*64 + lane*2;
        if (o0 < S2O){
            unsigned long long accA[8], accB[8];
#pragma unroll
            for (int j=0;j<8;j++){ accA[j]=0ull; accB[j]=0ull; }
#pragma unroll 4
            for (int k=0;k<E_;k++){
                float2 wp2 = *(const float2*)(g_W2 + k*S2O + o0);
                unsigned long long wa, wb;
                DUP2(wa, wp2.x); DUP2(wb, wp2.y);
                const ulonglong2* xr = (const ulonglong2*)(XsT + k*XP);
                ulonglong2 x0 = xr[0], x1 = xr[1], x2 = xr[2], x3 = xr[3];
                FMA2(accA[0], x0.x, wa); FMA2(accA[1], x0.y, wa);
                FMA2(accA[2], x1.x, wa); FMA2(accA[3], x1.y, wa);
                FMA2(accA[4], x2.x, wa); FMA2(accA[5], x2.y, wa);
                FMA2(accA[6], x3.x, wa); FMA2(accA[7], x3.y, wa);
                FMA2(accB[0], x0.x, wb); FMA2(accB[1], x0.y, wb);
                FMA2(accB[2], x1.x, wb); FMA2(accB[3], x1.y, wb);
                FMA2(accB[4], x2.x, wb); FMA2(accB[5], x2.y, wb);
                FMA2(accB[6], x3.x, wb); FMA2(accB[7], x3.y, wb);
            }
#pragma unroll
            for (int j=0;j<8;j++){
                float lo, hi;
                UNPK(lo, hi, accA[j]);
                Os[o0*OP + 2*j]       = lo;
                Os[o0*OP + 2*j+1]     = hi;
                UNPK(lo, hi, accB[j]);
                Os[(o0+1)*OP + 2*j]   = lo;
                Os[(o0+1)*OP + 2*j+1] = hi;
            }
        }
    }
    __syncthreads();

    float pgb0 = pgb[0];
    for (int i = tid; i < RB*E_; i += 256){
        int r = i/E_, e = i%E_;
        float p    = 1.f/(1.f+__expf(-(Os[96*OP+r] + pgb0)));
        float cand = tanhf(Os[e*OP+r] + mwb[e]);
        float mem  = XsT[(E_+e)*XP + r];
        out_memory[(b0+r)*E_ + e] = (1.f-p)*mem + p*cand;
    }
    for (int i = tid; i < RB*V_; i += 256){
        int r = i/V_, v = i%V_;
        float y = Os[(97+v)*OP + r];
        out_logits[(b0+r)*V_ + v] = rs_s[r]*(y - mu_s[r]*g_hg[v]) + g_hc1[v];
    }
}

// ================================== launch ==================================
extern "C" void kernel_launch(void* const* d_in, const int* in_sizes, int n_in,
                              void* d_out, int out_size)
{
    const int*   cidx = (const int*)  d_in[0];
    const int*   hist = (const int*)  d_in[1];
    const float* hid  = (const float*)d_in[2];
    const float* mem  = (const float*)d_in[3];
    const float* tok  = (const float*)d_in[4];
    const float* pos  = (const float*)d_in[5];
    const float* ipw  = (const float*)d_in[6];
    const float* ipb  = (const float*)d_in[7];
    const float* opw  = (const float*)d_in[8];
    const float* opb  = (const float*)d_in[9];
    const float* gih  = (const float*)d_in[10];
    const float* ghh  = (const float*)d_in[11];
    const float* gbih = (const float*)d_in[12];
    const float* gbhh = (const float*)d_in[13];
    const float* pgw  = (const float*)d_in[14];
    const float* pgb  = (const float*)d_in[15];
    const float* mww  = (const float*)d_in[16];
    const float* mwb  = (const float*)d_in[17];
    const float* lng  = (const float*)d_in[18];
    const float* lnb  = (const float*)d_in[19];
    const float* hdw  = (const float*)d_in[20];
    const float* hdb  = (const float*)d_in[21];

    float* out         = (float*)d_out;
    float* out_logits  = out;
    float* out_hidden  = out + (size_t)B_*V_;
    float* out_memory  = out + (size_t)B_*V_ + (size_t)B_*E_;

    cudaFuncSetAttribute(k2_attn, cudaFuncAttributeMaxDynamicSharedMemorySize,
                         K2_SMEM_BYTES);
    cudaFuncSetAttribute(k3_gru,  cudaFuncAttributeMaxDynamicSharedMemorySize,
                         K3_SMEM_FLOATS*4);

    k1_all<<<(K1_TOTAL + 255)/256, 256>>>(tok,pos,ipw,ipb,opw,opb,
                                          gih,ghh,gbih,gbhh,pgw,mww,
                                          lng,lnb,hdw,hdb);
    k2_attn<<<B_/BB, 256, K2_SMEM_BYTES>>>(hist);
    k3_gru <<<B_/RB, 256, K3_SMEM_FLOATS*4>>>(cidx, hid, mem, mwb, pgb,
                                              out_logits, out_hidden, out_memory);
}